// round 1
// baseline (speedup 1.0000x reference)
#include <cuda_runtime.h>
#include <mma.h>
#include <cstdint>

using namespace nvcuda;

#define T_TOK 8192
#define DIMD  1024
#define HID   2816
#define NE    8

#define BM 128
#define BN 64
#define BK 16
#define LDT 20   // BK + 4 pad (bank-conflict mitigation; multiple of 4 floats = 16B)

// ---------------- scratch (static __device__: allocation-free) ----------------
__device__ int   g_counts[NE];
__device__ int   g_list [NE * T_TOK];
__device__ float g_wlist[NE * T_TOK];
// activation scratch: segment 0 = shared expert (T rows), segments 1..8 = experts
// (padded to T rows each so out-of-count tiles can't corrupt neighbors)
__device__ float g_act[(size_t)(NE + 1) * T_TOK * HID];   // ~830 MB, zero-init .bss

// ---------------- cp.async helpers ----------------
__device__ __forceinline__ void cp_async16(uint32_t dst, const void* src) {
    asm volatile("cp.async.ca.shared.global [%0], [%1], 16;\n" :: "r"(dst), "l"(src));
}
__device__ __forceinline__ void smem_zero16(uint32_t dst) {
    asm volatile("st.shared.v4.b32 [%0], {%1,%1,%1,%1};\n" :: "r"(dst), "r"(0));
}
#define CP_COMMIT() asm volatile("cp.async.commit_group;\n")
#define CP_WAIT0()  asm volatile("cp.async.wait_group 0;\n")

// ============================================================================
// Gate: logits -> top2 -> normalized weights + per-expert token lists
// ============================================================================
__global__ __launch_bounds__(256) void gate_kernel(const float* __restrict__ x,
                                                   const float* __restrict__ gw)
{
    __shared__ float sgw[NE * DIMD];   // 32 KB
    for (int i = threadIdx.x; i < NE * DIMD; i += 256) sgw[i] = gw[i];
    __syncthreads();

    int warp = threadIdx.x >> 5, lane = threadIdx.x & 31;
    int t = blockIdx.x * 8 + warp;   // grid = T/8, exact
    const float* xp = x + (size_t)t * DIMD;

    float acc[NE];
#pragma unroll
    for (int e = 0; e < NE; e++) acc[e] = 0.f;
    for (int k = lane; k < DIMD; k += 32) {
        float xv = xp[k];
#pragma unroll
        for (int e = 0; e < NE; e++) acc[e] += xv * sgw[e * DIMD + k];
    }
#pragma unroll
    for (int e = 0; e < NE; e++) {
#pragma unroll
        for (int o = 16; o > 0; o >>= 1) acc[e] += __shfl_xor_sync(0xffffffffu, acc[e], o);
    }
    if (lane == 0) {
        int e0 = 0; float l0 = acc[0];
#pragma unroll
        for (int e = 1; e < NE; e++) if (acc[e] > l0) { l0 = acc[e]; e0 = e; }
        int e1 = (e0 == 0) ? 1 : 0; float l1 = acc[e1];
#pragma unroll
        for (int e = 0; e < NE; e++) if (e != e0 && acc[e] > l1) { l1 = acc[e]; e1 = e; }
        // softmax(top2)/sum(top2) == logistic of logit gap (Z cancels; +1e-20 negligible)
        float w0 = 1.f / (1.f + __expf(l1 - l0));
        float w1 = 1.f - w0;
        int p0 = atomicAdd(&g_counts[e0], 1);
        g_list[e0 * T_TOK + p0] = t;  g_wlist[e0 * T_TOK + p0] = w0;
        int p1 = atomicAdd(&g_counts[e1], 1);
        g_list[e1 * T_TOK + p1] = t;  g_wlist[e1 * T_TOK + p1] = w1;
    }
}

// ============================================================================
// GEMM1: g = silu(X_gathered @ W1^T) * (X_gathered @ W3^T), tf32 WMMA
// grid = (T/BM, HID/BN, NE+1); seg 0 = shared expert
// ============================================================================
__global__ __launch_bounds__(256, 2)
void gemm1_kernel(const float* __restrict__ x,
                  const float* __restrict__ w1, const float* __restrict__ w3,
                  const float* __restrict__ sw1, const float* __restrict__ sw3)
{
    int seg = blockIdx.z;
    int count; const int* list; const float* B1p; const float* B3p;
    if (seg == 0) { count = T_TOK; list = nullptr; B1p = sw1; B3p = sw3; }
    else {
        int e = seg - 1;
        count = g_counts[e];
        list  = g_list + e * T_TOK;
        B1p = w1 + (size_t)e * HID * DIMD;
        B3p = w3 + (size_t)e * HID * DIMD;
    }
    int m0 = blockIdx.x * BM;
    if (m0 >= count) return;
    int n0 = blockIdx.y * BN;

    __shared__ __align__(16) float smem[2 * BM * LDT + 4 * BN * LDT];  // 40960 B
    float* sA  = smem;                              // [2][BM*LDT]
    float* sB1 = smem + 2 * BM * LDT;               // [2][BN*LDT]
    float* sB3 = smem + 2 * BM * LDT + 2 * BN * LDT;

    int tid = threadIdx.x;
    // A: 512 16B chunks (128 rows x 4 chunks), 2 per thread, gathered rows
    int c0 = tid, c1 = tid + 256;
    int ar0 = c0 >> 2, ak0 = (c0 & 3) * 4;
    int ar1 = c1 >> 2, ak1 = (c1 & 3) * 4;
    int gr0 = m0 + ar0, gr1 = m0 + ar1;
    bool v0 = gr0 < count, v1 = gr1 < count;
    const float* asrc0 = v0 ? x + (size_t)(list ? list[gr0] : gr0) * DIMD + ak0 : nullptr;
    const float* asrc1 = v1 ? x + (size_t)(list ? list[gr1] : gr1) * DIMD + ak1 : nullptr;
    // B: 256 chunks, 1 per thread
    int br = tid >> 2, bk = (tid & 3) * 4;
    const float* b1src = B1p + (size_t)(n0 + br) * DIMD + bk;
    const float* b3src = B3p + (size_t)(n0 + br) * DIMD + bk;

    uint32_t sA_b  = (uint32_t)__cvta_generic_to_shared(sA);
    uint32_t sB1_b = (uint32_t)__cvta_generic_to_shared(sB1);
    uint32_t sB3_b = (uint32_t)__cvta_generic_to_shared(sB3);
    uint32_t adst0 = (uint32_t)((ar0 * LDT + ak0) * 4);
    uint32_t adst1 = (uint32_t)((ar1 * LDT + ak1) * 4);
    uint32_t bdst  = (uint32_t)((br * LDT + bk) * 4);

    auto load_stage = [&](int s, int k0) {
        uint32_t ao = sA_b + (uint32_t)(s * BM * LDT * 4);
        if (v0) cp_async16(ao + adst0, asrc0 + k0); else smem_zero16(ao + adst0);
        if (v1) cp_async16(ao + adst1, asrc1 + k0); else smem_zero16(ao + adst1);
        cp_async16(sB1_b + (uint32_t)(s * BN * LDT * 4) + bdst, b1src + k0);
        cp_async16(sB3_b + (uint32_t)(s * BN * LDT * 4) + bdst, b3src + k0);
        CP_COMMIT();
    };

    wmma::fragment<wmma::accumulator, 16, 16, 8, float> fc1[2][2], fc3[2][2];
#pragma unroll
    for (int i = 0; i < 2; i++)
#pragma unroll
        for (int j = 0; j < 2; j++) { wmma::fill_fragment(fc1[i][j], 0.f); wmma::fill_fragment(fc3[i][j], 0.f); }

    int warp = tid >> 5;
    int wm = (warp >> 1) * 32, wn = (warp & 1) * 32;

    load_stage(0, 0);
    const int NK = DIMD / BK;  // 64
    for (int kt = 0; kt < NK; kt++) {
        CP_WAIT0();
        __syncthreads();
        if (kt + 1 < NK) load_stage((kt + 1) & 1, (kt + 1) * BK);
        int s = kt & 1;
        const float* A  = sA  + s * BM * LDT;
        const float* Bb1 = sB1 + s * BN * LDT;
        const float* Bb3 = sB3 + s * BN * LDT;
#pragma unroll
        for (int kk = 0; kk < BK; kk += 8) {
            wmma::fragment<wmma::matrix_a, 16, 16, 8, wmma::precision::tf32, wmma::row_major> fa[2];
            wmma::fragment<wmma::matrix_b, 16, 16, 8, wmma::precision::tf32, wmma::col_major> f1[2], f3[2];
#pragma unroll
            for (int i = 0; i < 2; i++) {
                wmma::load_matrix_sync(fa[i], A + (wm + i * 16) * LDT + kk, LDT);
#pragma unroll
                for (int el = 0; el < fa[i].num_elements; el++)
                    fa[i].x[el] = wmma::__float_to_tf32(fa[i].x[el]);
            }
#pragma unroll
            for (int j = 0; j < 2; j++) {
                wmma::load_matrix_sync(f1[j], Bb1 + (wn + j * 16) * LDT + kk, LDT);
                wmma::load_matrix_sync(f3[j], Bb3 + (wn + j * 16) * LDT + kk, LDT);
#pragma unroll
                for (int el = 0; el < f1[j].num_elements; el++) {
                    f1[j].x[el] = wmma::__float_to_tf32(f1[j].x[el]);
                    f3[j].x[el] = wmma::__float_to_tf32(f3[j].x[el]);
                }
            }
#pragma unroll
            for (int i = 0; i < 2; i++)
#pragma unroll
                for (int j = 0; j < 2; j++) {
                    wmma::mma_sync(fc1[i][j], fa[i], f1[j], fc1[i][j]);
                    wmma::mma_sync(fc3[i][j], fa[i], f3[j], fc3[i][j]);
                }
        }
    }

    // epilogue: silu(h1) * h3, direct store into padded segment (oob rows are zeros)
    float* gout = g_act + (size_t)seg * T_TOK * HID;
#pragma unroll
    for (int i = 0; i < 2; i++)
#pragma unroll
        for (int j = 0; j < 2; j++) {
#pragma unroll
            for (int el = 0; el < fc1[i][j].num_elements; el++) {
                float v1 = fc1[i][j].x[el];
                float sl = v1 / (1.f + __expf(-v1));
                fc1[i][j].x[el] = sl * fc3[i][j].x[el];
            }
            wmma::store_matrix_sync(gout + (size_t)(m0 + wm + i * 16) * HID + (n0 + wn + j * 16),
                                    fc1[i][j], HID, wmma::mem_row_major);
        }
}

// ============================================================================
// GEMM2: y[tok] += weight * (G_seg @ W2^T); scatter-add epilogue
// grid = (T/BM, DIMD/BN, NE+1)
// ============================================================================
__global__ __launch_bounds__(256, 2)
void gemm2_kernel(const float* __restrict__ w2, const float* __restrict__ sw2,
                  float* __restrict__ y)
{
    int seg = blockIdx.z;
    int count; const int* list; const float* wl; const float* Bp;
    if (seg == 0) { count = T_TOK; list = nullptr; wl = nullptr; Bp = sw2; }
    else {
        int e = seg - 1;
        count = g_counts[e];
        list  = g_list  + e * T_TOK;
        wl    = g_wlist + e * T_TOK;
        Bp = w2 + (size_t)e * DIMD * HID;
    }
    int m0 = blockIdx.x * BM;
    if (m0 >= count) return;
    int n0 = blockIdx.y * BN;
    const float* Ap = g_act + (size_t)seg * T_TOK * HID;

    __shared__ __align__(16) float smem[BM * BN];   // 32 KB; pipeline uses first 7680 floats
    float* sA = smem;                 // [2][BM*LDT] = 5120
    float* sB = smem + 2 * BM * LDT;  // [2][BN*LDT] = 2560

    int tid = threadIdx.x;
    int c0 = tid, c1 = tid + 256;
    int ar0 = c0 >> 2, ak0 = (c0 & 3) * 4;
    int ar1 = c1 >> 2, ak1 = (c1 & 3) * 4;
    bool v0 = (m0 + ar0) < count, v1 = (m0 + ar1) < count;
    const float* asrc0 = Ap + (size_t)(m0 + ar0) * HID + ak0;
    const float* asrc1 = Ap + (size_t)(m0 + ar1) * HID + ak1;
    int br = tid >> 2, bk = (tid & 3) * 4;
    const float* bsrc = Bp + (size_t)(n0 + br) * HID + bk;

    uint32_t sA_b = (uint32_t)__cvta_generic_to_shared(sA);
    uint32_t sB_b = (uint32_t)__cvta_generic_to_shared(sB);
    uint32_t adst0 = (uint32_t)((ar0 * LDT + ak0) * 4);
    uint32_t adst1 = (uint32_t)((ar1 * LDT + ak1) * 4);
    uint32_t bdst  = (uint32_t)((br * LDT + bk) * 4);

    auto load_stage = [&](int s, int k0) {
        uint32_t ao = sA_b + (uint32_t)(s * BM * LDT * 4);
        if (v0) cp_async16(ao + adst0, asrc0 + k0); else smem_zero16(ao + adst0);
        if (v1) cp_async16(ao + adst1, asrc1 + k0); else smem_zero16(ao + adst1);
        cp_async16(sB_b + (uint32_t)(s * BN * LDT * 4) + bdst, bsrc + k0);
        CP_COMMIT();
    };

    wmma::fragment<wmma::accumulator, 16, 16, 8, float> fc[2][2];
#pragma unroll
    for (int i = 0; i < 2; i++)
#pragma unroll
        for (int j = 0; j < 2; j++) wmma::fill_fragment(fc[i][j], 0.f);

    int warp = tid >> 5;
    int wm = (warp >> 1) * 32, wn = (warp & 1) * 32;

    load_stage(0, 0);
    const int NK = HID / BK;  // 176
    for (int kt = 0; kt < NK; kt++) {
        CP_WAIT0();
        __syncthreads();
        if (kt + 1 < NK) load_stage((kt + 1) & 1, (kt + 1) * BK);
        int s = kt & 1;
        const float* A  = sA + s * BM * LDT;
        const float* Bb = sB + s * BN * LDT;
#pragma unroll
        for (int kk = 0; kk < BK; kk += 8) {
            wmma::fragment<wmma::matrix_a, 16, 16, 8, wmma::precision::tf32, wmma::row_major> fa[2];
            wmma::fragment<wmma::matrix_b, 16, 16, 8, wmma::precision::tf32, wmma::col_major> fb[2];
#pragma unroll
            for (int i = 0; i < 2; i++) {
                wmma::load_matrix_sync(fa[i], A + (wm + i * 16) * LDT + kk, LDT);
#pragma unroll
                for (int el = 0; el < fa[i].num_elements; el++)
                    fa[i].x[el] = wmma::__float_to_tf32(fa[i].x[el]);
            }
#pragma unroll
            for (int j = 0; j < 2; j++) {
                wmma::load_matrix_sync(fb[j], Bb + (wn + j * 16) * LDT + kk, LDT);
#pragma unroll
                for (int el = 0; el < fb[j].num_elements; el++)
                    fb[j].x[el] = wmma::__float_to_tf32(fb[j].x[el]);
            }
#pragma unroll
            for (int i = 0; i < 2; i++)
#pragma unroll
                for (int j = 0; j < 2; j++)
                    wmma::mma_sync(fc[i][j], fa[i], fb[j], fc[i][j]);
        }
    }

    // epilogue: stage to smem, then weighted scatter-add with row guard
    __syncthreads();
#pragma unroll
    for (int i = 0; i < 2; i++)
#pragma unroll
        for (int j = 0; j < 2; j++)
            wmma::store_matrix_sync(smem + (wm + i * 16) * BN + wn + j * 16,
                                    fc[i][j], BN, wmma::mem_row_major);
    __syncthreads();
    for (int it = tid; it < BM * BN; it += 256) {
        int r = it >> 6, n = it & 63;
        int gr = m0 + r;
        if (gr < count) {
            int tok = list ? list[gr] : gr;
            float w = wl ? wl[gr] : 1.f;
            atomicAdd(&y[(size_t)tok * DIMD + n0 + n], w * smem[it]);
        }
    }
}

// ============================================================================
extern "C" void kernel_launch(void* const* d_in, const int* in_sizes, int n_in,
                              void* d_out, int out_size)
{
    const float* x   = (const float*)d_in[0];
    const float* gw  = (const float*)d_in[1];
    const float* w1  = (const float*)d_in[2];
    const float* w2  = (const float*)d_in[3];
    const float* w3  = (const float*)d_in[4];
    const float* sw1 = (const float*)d_in[5];
    const float* sw2 = (const float*)d_in[6];
    const float* sw3 = (const float*)d_in[7];
    float* y = (float*)d_out;

    void* cptr = nullptr;
    cudaGetSymbolAddress(&cptr, g_counts);
    cudaMemsetAsync(cptr, 0, NE * sizeof(int));
    cudaMemsetAsync(y, 0, (size_t)T_TOK * DIMD * sizeof(float));

    gate_kernel<<<T_TOK / 8, 256>>>(x, gw);
    gemm1_kernel<<<dim3(T_TOK / BM, HID / BN, NE + 1), 256>>>(x, w1, w3, sw1, sw3);
    gemm2_kernel<<<dim3(T_TOK / BM, DIMD / BN, NE + 1), 256>>>(w2, sw2, y);
}

// round 7
// speedup vs baseline: 3.3085x; 3.3085x over previous
#include <cuda_runtime.h>
#include <cuda_fp16.h>
#include <mma.h>
#include <cstdint>

using namespace nvcuda;

#define T_TOK 8192
#define DIMD  1024
#define HID   2816
#define NE    8

#define BM 128
#define BN 128
#define BK 32
#define LDT 40            // halves per smem row (32 + 8 pad = 80B pitch)
#define STG_LD 132        // floats per staging row

#define TILE_H   (BM * LDT)            // 5120 halves per tile
#define STAGE1_H (3 * TILE_H)          // A, B1, B3
#define STAGE2_H (2 * TILE_H)          // A, B
#define SMEM1 (3 * STAGE1_H * 2)       // 92160 B (>= staging 67584)
#define SMEM2 (128 * STG_LD * 4)       // 67584 B (>= pipeline 61440)

#define NK1 (DIMD / BK)   // 32
#define NK2 (HID / BK)    // 88

// ---------------- static scratch (allocation-free) ----------------
__device__ int    g_counts[NE];
__device__ int    g_list[NE * T_TOK];
__device__ int    g_me[2 * T_TOK];
__device__ int    g_mp[2 * T_TOK];
__device__ float  g_mw[2 * T_TOK];
__device__ __half g_xh  [(size_t)T_TOK * DIMD];
__device__ __half g_w1h [(size_t)NE * HID * DIMD];
__device__ __half g_w3h [(size_t)NE * HID * DIMD];
__device__ __half g_w2h [(size_t)NE * DIMD * HID];
__device__ __half g_sw1h[(size_t)HID * DIMD];
__device__ __half g_sw3h[(size_t)HID * DIMD];
__device__ __half g_sw2h[(size_t)DIMD * HID];
__device__ __half g_acth[(size_t)(NE + 1) * T_TOK * HID];   // padded segments
__device__ float  g_part[(size_t)(NE + 1) * T_TOK * DIMD];  // padded segments

// ---------------- helpers ----------------
__device__ __forceinline__ void cp16(uint32_t d, const void* s) {
    asm volatile("cp.async.ca.shared.global [%0], [%1], 16;\n" :: "r"(d), "l"(s));
}
#define CPCOMMIT() asm volatile("cp.async.commit_group;\n" ::: "memory")
#define CPWAIT1()  asm volatile("cp.async.wait_group 1;\n" ::: "memory")

// ============================================================================
// f32 -> f16 conversion pre-pass (4 elements / thread)
// ============================================================================
__global__ __launch_bounds__(256) void tohalf_kernel(const float* __restrict__ src,
                                                     __half* __restrict__ dst, int n4)
{
    int i = blockIdx.x * 256 + threadIdx.x;
    if (i < n4) {
        float4 v = ((const float4*)src)[i];
        __half2 a = __floats2half2_rn(v.x, v.y);
        __half2 b = __floats2half2_rn(v.z, v.w);
        ((__half2*)dst)[2 * i]     = a;
        ((__half2*)dst)[2 * i + 1] = b;
    }
}

// ============================================================================
// Gate: logits -> top2 -> normalized weights + lists + inverse map
// ============================================================================
__global__ __launch_bounds__(256) void gate_kernel(const float* __restrict__ x,
                                                   const float* __restrict__ gw)
{
    __shared__ float sgw[NE * DIMD];
    for (int i = threadIdx.x; i < NE * DIMD; i += 256) sgw[i] = gw[i];
    __syncthreads();

    int warp = threadIdx.x >> 5, lane = threadIdx.x & 31;
    int t = blockIdx.x * 8 + warp;
    const float* xp = x + (size_t)t * DIMD;

    float acc[NE];
#pragma unroll
    for (int e = 0; e < NE; e++) acc[e] = 0.f;
    for (int k = lane; k < DIMD; k += 32) {
        float xv = xp[k];
#pragma unroll
        for (int e = 0; e < NE; e++) acc[e] += xv * sgw[e * DIMD + k];
    }
#pragma unroll
    for (int e = 0; e < NE; e++)
#pragma unroll
        for (int o = 16; o > 0; o >>= 1) acc[e] += __shfl_xor_sync(0xffffffffu, acc[e], o);

    if (lane == 0) {
        int e0 = 0; float l0 = acc[0];
#pragma unroll
        for (int e = 1; e < NE; e++) if (acc[e] > l0) { l0 = acc[e]; e0 = e; }
        int e1 = (e0 == 0) ? 1 : 0; float l1 = acc[e1];
#pragma unroll
        for (int e = 0; e < NE; e++) if (e != e0 && acc[e] > l1) { l1 = acc[e]; e1 = e; }
        float w0 = 1.f / (1.f + __expf(l1 - l0));   // softmax(top2) renormalized
        float w1 = 1.f - w0;
        int p0 = atomicAdd(&g_counts[e0], 1);
        g_list[e0 * T_TOK + p0] = t;
        int p1 = atomicAdd(&g_counts[e1], 1);
        g_list[e1 * T_TOK + p1] = t;
        g_me[2 * t] = e0; g_me[2 * t + 1] = e1;
        g_mp[2 * t] = p0; g_mp[2 * t + 1] = p1;
        g_mw[2 * t] = w0; g_mw[2 * t + 1] = w1;
    }
}

// ============================================================================
// GEMM1 (fp16 wmma): act = silu(X W1^T) * (X W3^T)   [per segment, gathered X]
// grid = (64, 22, 9); CTA tile 128x128, dual-B
// ============================================================================
__global__ __launch_bounds__(256, 1) void gemm1_kernel()
{
    extern __shared__ char smem[];
    const int tid = threadIdx.x, wid = tid >> 5;

    int seg = blockIdx.z;
    int count; const int* list; const __half* B1p; const __half* B3p;
    if (seg == 0) { count = T_TOK; list = nullptr; B1p = g_sw1h; B3p = g_sw3h; }
    else {
        int e = seg - 1;
        count = g_counts[e];
        list  = g_list + e * T_TOK;
        B1p = g_w1h + (size_t)e * HID * DIMD;
        B3p = g_w3h + (size_t)e * HID * DIMD;
    }
    int m0 = blockIdx.x * BM;
    if (m0 >= count) return;
    int n0 = blockIdx.y * BN;

    __half* sH = (__half*)smem;
    uint32_t sbase = (uint32_t)__cvta_generic_to_shared(sH);

    // per-thread chunk map: 1536 16B-chunks / stage, 6 per thread
    const __half* srcp[6]; uint32_t dsto[6];
#pragma unroll
    for (int i = 0; i < 6; i++) {
        int q = tid + 256 * i;
        int tile = q >> 9;            // 0=A, 1=B1, 2=B3
        int r = (q >> 2) & 127;
        int c = q & 3;                // 16B chunk within 32-half row
        const __half* s;
        if (tile == 0) {
            int gr = m0 + r;
            int tok = (gr < count) ? (list ? list[gr] : gr) : 0;
            s = g_xh + (size_t)tok * DIMD + c * 8;
        } else if (tile == 1) s = B1p + (size_t)(n0 + r) * DIMD + c * 8;
        else                  s = B3p + (size_t)(n0 + r) * DIMD + c * 8;
        srcp[i] = s;
        dsto[i] = (uint32_t)((tile * TILE_H + r * LDT + c * 8) * 2);
    }

    auto load_stage = [&](int s, int kt) {
        uint32_t base = sbase + (uint32_t)(s * STAGE1_H * 2);
#pragma unroll
        for (int i = 0; i < 6; i++) cp16(base + dsto[i], srcp[i] + kt * BK);
        CPCOMMIT();
    };

    wmma::fragment<wmma::accumulator, 16, 16, 16, float> fc1[2][4], fc3[2][4];
#pragma unroll
    for (int i = 0; i < 2; i++)
#pragma unroll
        for (int j = 0; j < 4; j++) { wmma::fill_fragment(fc1[i][j], 0.f); wmma::fill_fragment(fc3[i][j], 0.f); }

    int wm = (wid & 3) * 32, wn = (wid >> 2) * 64;

    load_stage(0, 0);
    load_stage(1, 1);

    for (int kt = 0; kt < NK1; kt++) {
        CPWAIT1();
        __syncthreads();
        if (kt + 2 < NK1) load_stage((kt + 2) % 3, kt + 2);
        else CPCOMMIT();   // keep group FIFO arithmetic uniform
        int s = kt % 3;
        const __half* A  = sH + s * STAGE1_H;
        const __half* B1 = A + TILE_H;
        const __half* B3 = A + 2 * TILE_H;
#pragma unroll
        for (int kk = 0; kk < BK; kk += 16) {
            wmma::fragment<wmma::matrix_a, 16, 16, 16, __half, wmma::row_major> fa[2];
#pragma unroll
            for (int i = 0; i < 2; i++)
                wmma::load_matrix_sync(fa[i], A + (wm + i * 16) * LDT + kk, LDT);
#pragma unroll
            for (int j = 0; j < 4; j++) {
                wmma::fragment<wmma::matrix_b, 16, 16, 16, __half, wmma::col_major> fb;
                wmma::load_matrix_sync(fb, B1 + (wn + j * 16) * LDT + kk, LDT);
#pragma unroll
                for (int i = 0; i < 2; i++) wmma::mma_sync(fc1[i][j], fa[i], fb, fc1[i][j]);
                wmma::load_matrix_sync(fb, B3 + (wn + j * 16) * LDT + kk, LDT);
#pragma unroll
                for (int i = 0; i < 2; i++) wmma::mma_sync(fc3[i][j], fa[i], fb, fc3[i][j]);
            }
        }
    }

    // epilogue: silu(h1)*h3 in registers -> float staging -> coalesced half store
    __syncthreads();
    float* stg = (float*)smem;
#pragma unroll
    for (int i = 0; i < 2; i++)
#pragma unroll
        for (int j = 0; j < 4; j++) {
#pragma unroll
            for (int el = 0; el < fc1[i][j].num_elements; el++) {
                float h1 = fc1[i][j].x[el];
                fc1[i][j].x[el] = (h1 / (1.f + __expf(-h1))) * fc3[i][j].x[el];
            }
            wmma::store_matrix_sync(stg + (wm + i * 16) * STG_LD + wn + j * 16,
                                    fc1[i][j], STG_LD, wmma::mem_row_major);
        }
    __syncthreads();

    __half* gout = g_acth + (size_t)seg * T_TOK * HID;
    for (int q = tid; q < 128 * 16; q += 256) {   // 16B chunks of 8 halves
        int row = q >> 4, c = q & 15;
        const float* p = stg + row * STG_LD + c * 8;
        __half2 h[4];
#pragma unroll
        for (int u = 0; u < 4; u++) h[u] = __floats2half2_rn(p[2 * u], p[2 * u + 1]);
        *(uint4*)&gout[(size_t)(m0 + row) * HID + n0 + c * 8] = *(uint4*)h;
    }
}

// ============================================================================
// GEMM2 (fp16 wmma): part[seg] = act[seg] @ W2^T   (partials, no atomics)
// grid = (64, 8, 9); CTA tile 128x128
// ============================================================================
__global__ __launch_bounds__(256, 1) void gemm2_kernel()
{
    extern __shared__ char smem[];
    const int tid = threadIdx.x, wid = tid >> 5;

    int seg = blockIdx.z;
    int count; const __half* Bp;
    if (seg == 0) { count = T_TOK; Bp = g_sw2h; }
    else { count = g_counts[seg - 1]; Bp = g_w2h + (size_t)(seg - 1) * DIMD * HID; }
    int m0 = blockIdx.x * BM;
    if (m0 >= count) return;
    int n0 = blockIdx.y * BN;
    const __half* Ap = g_acth + (size_t)seg * T_TOK * HID;

    __half* sH = (__half*)smem;
    uint32_t sbase = (uint32_t)__cvta_generic_to_shared(sH);

    const __half* srcp[4]; uint32_t dsto[4];
#pragma unroll
    for (int i = 0; i < 4; i++) {
        int q = tid + 256 * i;
        int tile = q >> 9;            // 0=A, 1=B
        int r = (q >> 2) & 127;
        int c = q & 3;
        const __half* s;
        if (tile == 0) s = Ap + (size_t)(m0 + r) * HID + c * 8;   // padded segment: always in-bounds
        else           s = Bp + (size_t)(n0 + r) * HID + c * 8;
        srcp[i] = s;
        dsto[i] = (uint32_t)((tile * TILE_H + r * LDT + c * 8) * 2);
    }

    auto load_stage = [&](int s, int kt) {
        uint32_t base = sbase + (uint32_t)(s * STAGE2_H * 2);
#pragma unroll
        for (int i = 0; i < 4; i++) cp16(base + dsto[i], srcp[i] + kt * BK);
        CPCOMMIT();
    };

    wmma::fragment<wmma::accumulator, 16, 16, 16, float> fc[2][4];
#pragma unroll
    for (int i = 0; i < 2; i++)
#pragma unroll
        for (int j = 0; j < 4; j++) wmma::fill_fragment(fc[i][j], 0.f);

    int wm = (wid & 3) * 32, wn = (wid >> 2) * 64;

    load_stage(0, 0);
    load_stage(1, 1);

    for (int kt = 0; kt < NK2; kt++) {
        CPWAIT1();
        __syncthreads();
        if (kt + 2 < NK2) load_stage((kt + 2) % 3, kt + 2);
        else CPCOMMIT();
        int s = kt % 3;
        const __half* A = sH + s * STAGE2_H;
        const __half* B = A + TILE_H;
#pragma unroll
        for (int kk = 0; kk < BK; kk += 16) {
            wmma::fragment<wmma::matrix_a, 16, 16, 16, __half, wmma::row_major> fa[2];
#pragma unroll
            for (int i = 0; i < 2; i++)
                wmma::load_matrix_sync(fa[i], A + (wm + i * 16) * LDT + kk, LDT);
#pragma unroll
            for (int j = 0; j < 4; j++) {
                wmma::fragment<wmma::matrix_b, 16, 16, 16, __half, wmma::col_major> fb;
                wmma::load_matrix_sync(fb, B + (wn + j * 16) * LDT + kk, LDT);
#pragma unroll
                for (int i = 0; i < 2; i++) wmma::mma_sync(fc[i][j], fa[i], fb, fc[i][j]);
            }
        }
    }

    __syncthreads();
    float* stg = (float*)smem;
#pragma unroll
    for (int i = 0; i < 2; i++)
#pragma unroll
        for (int j = 0; j < 4; j++)
            wmma::store_matrix_sync(stg + (wm + i * 16) * STG_LD + wn + j * 16,
                                    fc[i][j], STG_LD, wmma::mem_row_major);
    __syncthreads();

    float* pout = g_part + (size_t)seg * T_TOK * DIMD;
    for (int q = tid; q < 128 * 32; q += 256) {   // float4 chunks
        int row = q >> 5, c = q & 31;
        float4 v = *(float4*)&stg[row * STG_LD + c * 4];
        *(float4*)&pout[(size_t)(m0 + row) * DIMD + n0 + c * 4] = v;
    }
}

// ============================================================================
// Combine: y[t] = part[shared][t] + w0*part[e0][p0] + w1*part[e1][p1]
// ============================================================================
__global__ __launch_bounds__(256) void combine_kernel(float* __restrict__ y)
{
    int t = blockIdx.x;
    int e0 = g_me[2 * t], e1 = g_me[2 * t + 1];
    int p0 = g_mp[2 * t], p1 = g_mp[2 * t + 1];
    float w0 = g_mw[2 * t], w1 = g_mw[2 * t + 1];
    const float4* s0 = (const float4*)(g_part + (size_t)t * DIMD);
    const float4* pa = (const float4*)(g_part + ((size_t)(1 + e0) * T_TOK + p0) * DIMD);
    const float4* pb = (const float4*)(g_part + ((size_t)(1 + e1) * T_TOK + p1) * DIMD);
    float4* yo = (float4*)(y + (size_t)t * DIMD);
    int i = threadIdx.x;
    float4 a = s0[i], va = pa[i], vb = pb[i];
    yo[i] = make_float4(a.x + w0 * va.x + w1 * vb.x,
                        a.y + w0 * va.y + w1 * vb.y,
                        a.z + w0 * va.z + w1 * vb.z,
                        a.w + w0 * va.w + w1 * vb.w);
}

// ============================================================================
extern "C" void kernel_launch(void* const* d_in, const int* in_sizes, int n_in,
                              void* d_out, int out_size)
{
    const float* x   = (const float*)d_in[0];
    const float* gw  = (const float*)d_in[1];
    const float* w1  = (const float*)d_in[2];
    const float* w2  = (const float*)d_in[3];
    const float* w3  = (const float*)d_in[4];
    const float* sw1 = (const float*)d_in[5];
    const float* sw2 = (const float*)d_in[6];
    const float* sw3 = (const float*)d_in[7];
    float* y = (float*)d_out;

    void* cptr = nullptr;
    cudaGetSymbolAddress(&cptr, g_counts);
    cudaMemsetAsync(cptr, 0, NE * sizeof(int));

    void *xh, *w1h, *w3h, *w2h, *s1h, *s2h, *s3h;
    cudaGetSymbolAddress(&xh,  g_xh);
    cudaGetSymbolAddress(&w1h, g_w1h);
    cudaGetSymbolAddress(&w3h, g_w3h);
    cudaGetSymbolAddress(&w2h, g_w2h);
    cudaGetSymbolAddress(&s1h, g_sw1h);
    cudaGetSymbolAddress(&s2h, g_sw2h);
    cudaGetSymbolAddress(&s3h, g_sw3h);

    const int nx  = T_TOK * DIMD / 4;
    const int nw  = NE * HID * DIMD / 4;
    const int nsw = HID * DIMD / 4;
    tohalf_kernel<<<(nx  + 255) / 256, 256>>>(x,   (__half*)xh,  nx);
    tohalf_kernel<<<(nw  + 255) / 256, 256>>>(w1,  (__half*)w1h, nw);
    tohalf_kernel<<<(nw  + 255) / 256, 256>>>(w3,  (__half*)w3h, nw);
    tohalf_kernel<<<(nw  + 255) / 256, 256>>>(w2,  (__half*)w2h, nw);
    tohalf_kernel<<<(nsw + 255) / 256, 256>>>(sw1, (__half*)s1h, nsw);
    tohalf_kernel<<<(nsw + 255) / 256, 256>>>(sw2, (__half*)s2h, nsw);
    tohalf_kernel<<<(nsw + 255) / 256, 256>>>(sw3, (__half*)s3h, nsw);

    gate_kernel<<<T_TOK / 8, 256>>>(x, gw);

    cudaFuncSetAttribute(gemm1_kernel, cudaFuncAttributeMaxDynamicSharedMemorySize, SMEM1);
    cudaFuncSetAttribute(gemm2_kernel, cudaFuncAttributeMaxDynamicSharedMemorySize, SMEM2);

    gemm1_kernel<<<dim3(T_TOK / BM, HID / BN, NE + 1), 256, SMEM1>>>();
    gemm2_kernel<<<dim3(T_TOK / BM, DIMD / BN, NE + 1), 256, SMEM2>>>();
    combine_kernel<<<T_TOK, 256>>>(y);
}